// round 15
// baseline (speedup 1.0000x reference)
#include <cuda_runtime.h>
#include <stdint.h>

#define N_STEPS 50

// Output layout (flattened tuple, row-major, float32):
//   slot0 = Xn history [32,50,64,8]      @ 0          (post-sample state)
//   slot1 = En history [32,50,64,64,5]   @ 819200     (post-sample state)
//   slot2 = Xc history [32,50,64,8]      @ 33587200   (pre-step state)
//   slot3 = Ec history [32,50,64,64,5]   @ 34406400   (pre-step state)
#define OFF_EN  819200
#define OFF_XC  33587200
#define OFF_EC  34406400

#define N_PAIRS 2016          // 64 choose 2
#define N_EFLOAT4 8192000     // 32*50*64*80 float4 in the E post array

// Per-step derived keys (partitionable split) + precomputed log-prob tables.
__device__ uint2 g_kx[N_STEPS];
__device__ uint2 g_ke[N_STEPS];
__device__ float g_lqe[N_STEPS * 25];   // [k][l][c], D=5
__device__ float g_lqx[N_STEPS * 64];   // [k][l][c], D=8
__device__ unsigned short g_pair[N_PAIRS];            // i*64+j, i<j
__device__ unsigned char g_lab[32 * 50 * 64 * 64];    // [b][k][i][j] labels

// ---------------- Threefry-2x32 (JAX-exact: 20 rounds, 5 key injections) ----
__device__ __forceinline__ void tf2x32(uint32_t k0, uint32_t k1,
                                       uint32_t x0, uint32_t x1,
                                       uint32_t& o0, uint32_t& o1) {
    uint32_t ks2 = k0 ^ k1 ^ 0x1BD11BDAu;
    x0 += k0; x1 += k1;
#define TF_R(r) { x0 += x1; x1 = __funnelshift_l(x1, x1, (r)); x1 ^= x0; }
    TF_R(13) TF_R(15) TF_R(26) TF_R(6)
    x0 += k1;  x1 += ks2 + 1u;
    TF_R(17) TF_R(29) TF_R(16) TF_R(24)
    x0 += ks2; x1 += k0 + 2u;
    TF_R(13) TF_R(15) TF_R(26) TF_R(6)
    x0 += k0;  x1 += k1 + 3u;
    TF_R(17) TF_R(29) TF_R(16) TF_R(24)
    x0 += k1;  x1 += ks2 + 4u;
    TF_R(13) TF_R(15) TF_R(26) TF_R(6)
    x0 += ks2; x1 += k0 + 5u;
#undef TF_R
    o0 = x0; o1 = x1;
}

// Partitionable random_bits(32): element i -> XOR of both cipher words.
__device__ __forceinline__ uint32_t jax_bits32(uint2 key, uint32_t idx) {
    uint32_t o0, o1;
    tf2x32(key.x, key.y, 0u, idx, o0, o1);
    return o0 ^ o1;
}

// JAX gumbel from raw bits (bit-exact op sequence).
__device__ __forceinline__ float gumbel_from_bits(uint32_t bits) {
    const float TINY = 1.17549435082228751e-38f;
    float u = __uint_as_float((bits >> 9) | 0x3f800000u) - 1.0f;
    u = u + TINY;
    u = fmaxf(TINY, u);
    return -logf(-logf(u));
}

// ------- init: per-step keys + logq tables + pair table ----------------------
// One logq row, identical op order to the original serial version.
template <int D>
__device__ __forceinline__ void make_logq_row(const float* __restrict__ W,
                                              float gamma, int l,
                                              float* __restrict__ dst) {
    const float* row = W + l * D;
    float p[D];
    float m = row[0];
    for (int c = 1; c < D; c++) m = fmaxf(m, row[c]);
    float s = 0.0f;
    for (int c = 0; c < D; c++) { p[c] = expf(row[c] - m); s += p[c]; }
    for (int c = 0; c < D; c++) p[c] = (p[c] / s) * gamma;
    p[l] = 0.0f;
    float s2 = 0.0f;
    for (int c = 0; c < D; c++) s2 += p[c];
    p[l] = fmaxf(1.0f - s2, 0.0f);
    float t = 0.0f;
    for (int c = 0; c < D; c++) t += p[c];
    for (int c = 0; c < D; c++) dst[l * D + c] = logf(p[c] / t);
}

// Grid: 50 blocks (one per step k), 64 threads. Thread 0..7 -> X logq rows,
// 8..12 -> E logq rows, 13 -> keys, rest -> pair-table slice.
__global__ void init_kernel(const float* __restrict__ gammas,
                            const float* __restrict__ Wx,
                            const float* __restrict__ We) {
    const int k = blockIdx.x;
    const int t = threadIdx.x;
    const float gamma = gammas[k];
    if (t < 8) {
        make_logq_row<8>(Wx, gamma, t, &g_lqx[k * 64]);
    } else if (t < 13) {
        make_logq_row<5>(We, gamma, t - 8, &g_lqe[k * 25]);
    } else if (t == 13) {
        uint32_t f0, f1;
        tf2x32(0u, 42u, 0u, (uint32_t)k, f0, f1);    // fold_in(key(42), k)
        uint32_t a0, a1, b0, b1;
        tf2x32(f0, f1, 0u, 0u, a0, a1);              // split key[0]
        tf2x32(f0, f1, 0u, 1u, b0, b1);              // split key[1]
        g_kx[k] = make_uint2(a0, a1);
        g_ke[k] = make_uint2(b0, b1);
    }
    // pair table: p -> (i,j), i<j (block 0 only; j-fastest enumeration)
    if (blockIdx.x == 0) {
        for (int p = t; p < N_PAIRS; p += blockDim.x) {
            int rem = p, i = 0;
            while (rem >= 63 - i) { rem -= 63 - i; i++; }
            int j = i + 1 + rem;
            g_pair[p] = (unsigned short)(i * 64 + j);
        }
    }
}

// node_mask dtype detection (bool8 / int32 / float32).
__device__ __forceinline__ int detect_mask_mode(const void* p) {
    const unsigned char* u = (const unsigned char*)p;
    if (u[1] == 1) return 0;
    if (((const int*)p)[0] == 1) return 1;
    return 2;
}
__device__ __forceinline__ bool mask_val(const void* p, int mode, int idx) {
    if (mode == 0) return ((const unsigned char*)p)[idx] != 0;
    if (mode == 1) return ((const int*)p)[idx] != 0;
    return ((const float*)p)[idx] != 0.0f;
}

// --------------------------- chain kernel -----------------------------------
// Blocks 0..503: edge chains, densely packed: thread g = (b, pair p).
//   Every lane runs a chain (no diagonal/triangle waste). Labels (1 byte per
//   step) written to g_lab in both orientations; masked pairs write 0xFF.
// Blocks 504..519: node chains (one thread per (b,i)), write outputs directly.
__global__ __launch_bounds__(128, 8)
void chain_kernel(const float* __restrict__ X, const float* __restrict__ E,
                  const void* __restrict__ maskp, float* __restrict__ out) {
    __shared__ uint2 sKey[N_STEPS];
    __shared__ float sLq[N_STEPS * 64];
    __shared__ int sMode;

    const bool edge = blockIdx.x < 504;
    if (edge) {
        for (int t = threadIdx.x; t < N_STEPS; t += 128) sKey[t] = g_ke[t];
        for (int t = threadIdx.x; t < N_STEPS * 25; t += 128) sLq[t] = g_lqe[t];
    } else {
        for (int t = threadIdx.x; t < N_STEPS; t += 128) sKey[t] = g_kx[t];
        for (int t = threadIdx.x; t < N_STEPS * 64; t += 128) sLq[t] = g_lqx[t];
    }
    if (threadIdx.x == 0) sMode = detect_mask_mode(maskp);
    __syncthreads();
    const int mode = sMode;

    if (edge) {
        int g = blockIdx.x * 128 + threadIdx.x;      // 0..64511
        int b = g / N_PAIRS;
        int p = g - b * N_PAIRS;
        int ij = (int)g_pair[p];
        int i = ij >> 6, j = ij & 63;
        bool valid = mask_val(maskp, mode, b * 64 + i)
                  && mask_val(maskp, mode, b * 64 + j);
        unsigned char* lab = g_lab + (size_t)b * (50 * 4096);
        const int lo0 = i * 64 + j, lo1 = j * 64 + i;

        if (valid) {
            uint32_t gbase = (uint32_t)(((b * 64 + i) * 64 + j) * 5);
            const float* ep = E + ((size_t)(b * 4096) + ij) * 5;
            int l = 0;
            float bv = ep[0];
#pragma unroll
            for (int c = 1; c < 5; c++) { float v = ep[c]; if (v > bv) { bv = v; l = c; } }
#pragma unroll 2
            for (int k = 0; k < N_STEPS; k++) {
                uint2 key = sKey[k];
                float gg[5];
#pragma unroll
                for (int c = 0; c < 5; c++)
                    gg[c] = gumbel_from_bits(jax_bits32(key, gbase + c));
                const float* lq = &sLq[k * 25 + l * 5];
                float best = lq[0] + gg[0];
                int bi = 0;
#pragma unroll
                for (int c = 1; c < 5; c++) {
                    float sc = lq[c] + gg[c];
                    if (sc > best) { best = sc; bi = c; }
                }
                l = bi;
                lab[k * 4096 + lo0] = (unsigned char)l;
                lab[k * 4096 + lo1] = (unsigned char)l;
            }
        } else {
#pragma unroll 2
            for (int k = 0; k < N_STEPS; k++) {
                lab[k * 4096 + lo0] = 0xFFu;
                lab[k * 4096 + lo1] = 0xFFu;
            }
        }
    } else {
        // ------------------------- node chains ------------------------------
        int t = (blockIdx.x - 504) * 128 + threadIdx.x;  // 0..2047
        int b = t >> 6, i = t & 63;
        bool valid = mask_val(maskp, mode, b * 64 + i);
        uint32_t gbase = (uint32_t)((b * 64 + i) * 8);

        float in[8];
        const float* xp = X + (size_t)(b * 64 + i) * 8;
#pragma unroll
        for (int c = 0; c < 8; c++) in[c] = xp[c];

        float* postX = out + (size_t)b * 50 * 512 + (size_t)i * 8;
        float* preX  = out + OFF_XC + (size_t)b * 50 * 512 + (size_t)i * 8;

        if (valid) {
            int l = 0;
            float bv = in[0];
#pragma unroll
            for (int c = 1; c < 8; c++) if (in[c] > bv) { bv = in[c]; l = c; }
#pragma unroll 1
            for (int k = 0; k < N_STEPS; k++) {
                float* pp = preX  + (size_t)k * 512;
                float* sp = postX + (size_t)k * 512;
                if (k == 0) {
#pragma unroll
                    for (int c = 0; c < 8; c++) pp[c] = in[c];
                } else {
#pragma unroll
                    for (int c = 0; c < 8; c++) pp[c] = (c == l) ? 1.0f : 0.0f;
                }
                uint2 key = sKey[k];
                const float* lq = &sLq[k * 64 + l * 8];
                float best = 0.0f;
                int bi = 0;
#pragma unroll
                for (int c = 0; c < 8; c++) {
                    float gv = gumbel_from_bits(jax_bits32(key, gbase + c));
                    float sc = lq[c] + gv;
                    if (c == 0) best = sc;
                    else if (sc > best) { best = sc; bi = c; }
                }
                l = bi;
#pragma unroll
                for (int c = 0; c < 8; c++) sp[c] = (c == l) ? 1.0f : 0.0f;
            }
        } else {
#pragma unroll 2
            for (int k = 0; k < N_STEPS; k++) {
                float* pp = preX  + (size_t)k * 512;
                float* sp = postX + (size_t)k * 512;
#pragma unroll
                for (int c = 0; c < 8; c++) pp[c] = (k == 0) ? in[c] : 0.0f;
#pragma unroll
                for (int c = 0; c < 8; c++) sp[c] = 0.0f;
            }
        }
    }
}

// --------------------------- expansion kernel -------------------------------
// One float4 of the E post-array per thread (flat over 32*50*64*80).
// Each thread: expand labels -> one-hot float4, store post[b][k][i] row chunk,
// and store the SAME value as pre[b][k+1][i] (pre[k+1] == post[k]); threads
// with k==49 instead store pre[b][0][i] = raw E (the only pre slab that is
// not a post slab). Diagonal cells (j == i) force label 0xFF -> zeros.
__global__ __launch_bounds__(256)
void expand_kernel(const float* __restrict__ E, float* __restrict__ out) {
    int flat = blockIdx.x * 256 + threadIdx.x;
    if (flat >= N_EFLOAT4) return;
    int s = flat / 80;               // (b*50+k)*64 + i   (0..102399)
    int q = flat - s * 80;           // float4 within 320-float row
    int i = s & 63;
    int bk = s >> 6;                 // b*50 + k
    int k = bk % 50;

    const unsigned char* labRow = g_lab + (size_t)s * 64;  // = [b][k][i][*]
    int f0 = q * 4;
    float4 v;
    {
        float* vp = &v.x;
#pragma unroll
        for (int t = 0; t < 4; t++) {
            int f = f0 + t;
            int cl = f / 5;                  // j coordinate
            int ch = f - cl * 5;             // class index
            int L = (cl == i) ? 255 : (int)labRow[cl];
            vp[t] = (ch == L) ? 1.0f : 0.0f;
        }
    }
    *(float4*)(out + OFF_EN + (size_t)s * 320 + f0) = v;
    if (k < 49) {
        *(float4*)(out + OFF_EC + (size_t)(s + 64) * 320 + f0) = v;
    } else {
        int b = bk / 50;
        int s0 = s - 49 * 64;                // (b*50+0)*64 + i
        float4 raw = *(const float4*)(E + (size_t)b * 20480 + (size_t)i * 320 + f0);
        *(float4*)(out + OFF_EC + (size_t)s0 * 320 + f0) = raw;
    }
}

extern "C" void kernel_launch(void* const* d_in, const int* in_sizes, int n_in,
                              void* d_out, int out_size) {
    (void)in_sizes; (void)n_in; (void)out_size;
    const float* X      = (const float*)d_in[0];
    const float* E      = (const float*)d_in[1];
    const void*  maskp  = d_in[2];
    const float* gammas = (const float*)d_in[3];
    const float* Wx     = (const float*)d_in[4];
    const float* We     = (const float*)d_in[5];
    float* out = (float*)d_out;

    init_kernel<<<50, 64>>>(gammas, Wx, We);
    // 504 edge blocks (64512 pair chains) + 16 node blocks (2048 chains)
    chain_kernel<<<520, 128>>>(X, E, maskp, out);
    // 8,192,000 float4 / 256 = 32000 blocks
    expand_kernel<<<32000, 256>>>(E, out);
}

// round 17
// speedup vs baseline: 1.0013x; 1.0013x over previous
#include <cuda_runtime.h>
#include <stdint.h>

#define N_STEPS 50

// Output layout (flattened tuple, row-major, float32):
//   slot0 = Xn history [32,50,64,8]      @ 0          (post-sample state)
//   slot1 = En history [32,50,64,64,5]   @ 819200     (post-sample state)
//   slot2 = Xc history [32,50,64,8]      @ 33587200   (pre-step state)
//   slot3 = Ec history [32,50,64,64,5]   @ 34406400   (pre-step state)
#define OFF_EN  819200
#define OFF_XC  33587200
#define OFF_EC  34406400

#define N_PAIRS 2016          // 64 choose 2
#define N_EFLOAT4 8192000     // 32*50*64*80 float4 in the E post array
#define EDGE_BLOCKS 1008      // 64512 chains * 2 lanes / 128

__device__ unsigned char g_lab[32 * 50 * 64 * 64];    // [b][k][i][j] labels

// ---------------- Threefry-2x32 (JAX-exact: 20 rounds, 5 key injections) ----
__device__ __forceinline__ void tf2x32(uint32_t k0, uint32_t k1,
                                       uint32_t x0, uint32_t x1,
                                       uint32_t& o0, uint32_t& o1) {
    uint32_t ks2 = k0 ^ k1 ^ 0x1BD11BDAu;
    x0 += k0; x1 += k1;
#define TF_R(r) { x0 += x1; x1 = __funnelshift_l(x1, x1, (r)); x1 ^= x0; }
    TF_R(13) TF_R(15) TF_R(26) TF_R(6)
    x0 += k1;  x1 += ks2 + 1u;
    TF_R(17) TF_R(29) TF_R(16) TF_R(24)
    x0 += ks2; x1 += k0 + 2u;
    TF_R(13) TF_R(15) TF_R(26) TF_R(6)
    x0 += k0;  x1 += k1 + 3u;
    TF_R(17) TF_R(29) TF_R(16) TF_R(24)
    x0 += k1;  x1 += ks2 + 4u;
    TF_R(13) TF_R(15) TF_R(26) TF_R(6)
    x0 += ks2; x1 += k0 + 5u;
#undef TF_R
    o0 = x0; o1 = x1;
}

// Partitionable random_bits(32): element i -> XOR of both cipher words.
__device__ __forceinline__ uint32_t jax_bits32(uint2 key, uint32_t idx) {
    uint32_t o0, o1;
    tf2x32(key.x, key.y, 0u, idx, o0, o1);
    return o0 ^ o1;
}

// JAX gumbel from raw bits (bit-exact op sequence).
__device__ __forceinline__ float gumbel_from_bits(uint32_t bits) {
    const float TINY = 1.17549435082228751e-38f;
    float u = __uint_as_float((bits >> 9) | 0x3f800000u) - 1.0f;
    u = u + TINY;
    u = fmaxf(TINY, u);
    return -logf(-logf(u));
}

// One logq row, identical per-row op order to the original (bit-exact).
template <int D>
__device__ __forceinline__ void make_logq_row(const float* __restrict__ W,
                                              float gamma, int l,
                                              float* __restrict__ dst) {
    const float* row = W + l * D;
    float p[D];
    float m = row[0];
    for (int c = 1; c < D; c++) m = fmaxf(m, row[c]);
    float s = 0.0f;
    for (int c = 0; c < D; c++) { p[c] = expf(row[c] - m); s += p[c]; }
    for (int c = 0; c < D; c++) p[c] = (p[c] / s) * gamma;
    p[l] = 0.0f;
    float s2 = 0.0f;
    for (int c = 0; c < D; c++) s2 += p[c];
    p[l] = fmaxf(1.0f - s2, 0.0f);
    float t = 0.0f;
    for (int c = 0; c < D; c++) t += p[c];
    for (int c = 0; c < D; c++) dst[l * D + c] = logf(p[c] / t);
}

// node_mask dtype detection (bool8 / int32 / float32).
__device__ __forceinline__ int detect_mask_mode(const void* p) {
    const unsigned char* u = (const unsigned char*)p;
    if (u[1] == 1) return 0;
    if (((const int*)p)[0] == 1) return 1;
    return 2;
}
__device__ __forceinline__ bool mask_val(const void* p, int mode, int idx) {
    if (mode == 0) return ((const unsigned char*)p)[idx] != 0;
    if (mode == 1) return ((const int*)p)[idx] != 0;
    return ((const float*)p)[idx] != 0.0f;
}

// First-max merge across lanes: adopt partner iff strictly better, or equal
// with lower class index (== min index among maxima == serial first-max).
__device__ __forceinline__ void merge_argmax(float& best, int& bi,
                                             unsigned mask, int xorLane) {
    float pb = __shfl_xor_sync(mask, best, xorLane);
    int   pi = __shfl_xor_sync(mask, bi,   xorLane);
    if (pb > best || (pb == best && pi < bi)) { best = pb; bi = pi; }
}

// --------------------------- chain kernel -----------------------------------
// Blocks 0..1007: edge chains, 2 lanes per chain (lane0: classes 0-2,
//   lane1: classes 3-4). Labels written to g_lab both orientations.
// Blocks 1008..1071: node chains, 4 lanes per chain (2 classes each),
//   outputs written directly.
// Each block computes its own key/logq tables in SMEM (no init kernel).
__global__ __launch_bounds__(128, 8)
void chain_kernel(const float* __restrict__ X, const float* __restrict__ E,
                  const void* __restrict__ maskp,
                  const float* __restrict__ gammas,
                  const float* __restrict__ Wx, const float* __restrict__ We,
                  float* __restrict__ out) {
    __shared__ uint2 sKey[N_STEPS];
    __shared__ float sLq[N_STEPS * 64];
    __shared__ int sMode;

    const bool edge = blockIdx.x < EDGE_BLOCKS;
    const int t = threadIdx.x;

    // ---- in-block table construction (bit-identical per-row op order) ----
    if (edge) {
        for (int row = t; row < N_STEPS * 5; row += 128) {
            int k = row / 5, l = row - k * 5;
            make_logq_row<5>(We, gammas[k], l, &sLq[k * 25]);
        }
    } else {
        for (int row = t; row < N_STEPS * 8; row += 128) {
            int k = row >> 3, l = row & 7;
            make_logq_row<8>(Wx, gammas[k], l, &sLq[k * 64]);
        }
    }
    if (t < N_STEPS) {
        uint32_t f0, f1;
        tf2x32(0u, 42u, 0u, (uint32_t)t, f0, f1);    // fold_in(key(42), k)
        uint32_t a0, a1, b0, b1;
        tf2x32(f0, f1, 0u, 0u, a0, a1);              // split key[0] -> kx
        tf2x32(f0, f1, 0u, 1u, b0, b1);              // split key[1] -> ke
        sKey[t] = edge ? make_uint2(b0, b1) : make_uint2(a0, a1);
    }
    if (t == 0) sMode = detect_mask_mode(maskp);
    __syncthreads();
    const int mode = sMode;

    if (edge) {
        int g2 = blockIdx.x * 128 + t;               // 0..129023
        int chain = g2 >> 1;                          // 0..64511
        int r = g2 & 1;                               // lane role
        int b = chain / N_PAIRS;
        int p = chain - b * N_PAIRS;
        // p -> (i,j), i<j, j-fastest enumeration
        int rem = p, i = 0;
        while (rem >= 63 - i) { rem -= 63 - i; i++; }
        int j = i + 1 + rem;

        bool valid = mask_val(maskp, mode, b * 64 + i)
                  && mask_val(maskp, mode, b * 64 + j);
        unsigned char* lab = g_lab + (size_t)b * (50 * 4096);
        const int myLo = r ? (j * 64 + i) : (i * 64 + j);

        if (valid) {
            const unsigned mk = __activemask();
            uint32_t gbase = (uint32_t)(((b * 64 + i) * 64 + j) * 5);
            const float* ep = E + ((size_t)(b * 4096) + i * 64 + j) * 5;
            const int c0 = r ? 3 : 0;
            // initial label: lane-partial argmax of input, then merge
            float best; int bi;
            {
                best = ep[c0]; bi = c0;
                float v1 = ep[c0 + 1];
                if (v1 > best) { best = v1; bi = c0 + 1; }
                if (r == 0) {
                    float v2 = ep[2];
                    if (v2 > best) { best = v2; bi = 2; }
                }
            }
            merge_argmax(best, bi, mk, 1);
            int l = bi;
#pragma unroll 2
            for (int k = 0; k < N_STEPS; k++) {
                uint2 key = sKey[k];
                const float* lq = &sLq[k * 25 + l * 5];
                float g0 = gumbel_from_bits(jax_bits32(key, gbase + c0));
                float g1 = gumbel_from_bits(jax_bits32(key, gbase + c0 + 1));
                best = lq[c0] + g0; bi = c0;
                float sc = lq[c0 + 1] + g1;
                if (sc > best) { best = sc; bi = c0 + 1; }
                if (r == 0) {
                    float g2v = gumbel_from_bits(jax_bits32(key, gbase + 2));
                    sc = lq[2] + g2v;
                    if (sc > best) { best = sc; bi = 2; }
                }
                merge_argmax(best, bi, mk, 1);
                l = bi;
                lab[k * 4096 + myLo] = (unsigned char)l;
            }
        } else {
#pragma unroll 2
            for (int k = 0; k < N_STEPS; k++)
                lab[k * 4096 + myLo] = 0xFFu;
        }
    } else {
        // ------------------------- node chains ------------------------------
        int g4 = (blockIdx.x - EDGE_BLOCKS) * 128 + t;  // 0..8191
        int chain = g4 >> 2;                             // 0..2047
        int r = g4 & 3;                                  // lane role
        int b = chain >> 6, i = chain & 63;
        bool valid = mask_val(maskp, mode, b * 64 + i);
        uint32_t gbase = (uint32_t)((b * 64 + i) * 8);
        const int c0 = r * 2;

        const float* xp = X + (size_t)(b * 64 + i) * 8;
        float in0 = xp[c0], in1 = xp[c0 + 1];

        float* postX = out + (size_t)b * 50 * 512 + (size_t)i * 8;
        float* preX  = out + OFF_XC + (size_t)b * 50 * 512 + (size_t)i * 8;

        if (valid) {
            const unsigned mk = __activemask();
            float best = in0; int bi = c0;
            if (in1 > best) { best = in1; bi = c0 + 1; }
            merge_argmax(best, bi, mk, 1);
            merge_argmax(best, bi, mk, 2);
            int l = bi;
#pragma unroll 2
            for (int k = 0; k < N_STEPS; k++) {
                float* pp = preX  + (size_t)k * 512;
                float* sp = postX + (size_t)k * 512;
                if (k == 0) {
                    pp[c0] = in0; pp[c0 + 1] = in1;
                } else {
                    pp[c0]     = (c0     == l) ? 1.0f : 0.0f;
                    pp[c0 + 1] = (c0 + 1 == l) ? 1.0f : 0.0f;
                }
                uint2 key = sKey[k];
                const float* lq = &sLq[k * 64 + l * 8];
                float g0 = gumbel_from_bits(jax_bits32(key, gbase + c0));
                float g1 = gumbel_from_bits(jax_bits32(key, gbase + c0 + 1));
                best = lq[c0] + g0; bi = c0;
                float sc = lq[c0 + 1] + g1;
                if (sc > best) { best = sc; bi = c0 + 1; }
                merge_argmax(best, bi, mk, 1);
                merge_argmax(best, bi, mk, 2);
                l = bi;
                sp[c0]     = (c0     == l) ? 1.0f : 0.0f;
                sp[c0 + 1] = (c0 + 1 == l) ? 1.0f : 0.0f;
            }
        } else {
#pragma unroll 2
            for (int k = 0; k < N_STEPS; k++) {
                float* pp = preX  + (size_t)k * 512;
                float* sp = postX + (size_t)k * 512;
                pp[c0]     = (k == 0) ? in0 : 0.0f;
                pp[c0 + 1] = (k == 0) ? in1 : 0.0f;
                sp[c0] = 0.0f; sp[c0 + 1] = 0.0f;
            }
        }
    }
}

// --------------------------- expansion kernel -------------------------------
// One float4 of the E post-array per thread (flat over 32*50*64*80).
// Expand labels -> one-hot float4, store post[b][k][i] chunk and the same
// value as pre[b][k+1][i]; k==49 threads instead store pre[b][0][i] = raw E.
// Diagonal cells (j == i) force label 0xFF -> zeros.
__global__ __launch_bounds__(256)
void expand_kernel(const float* __restrict__ E, float* __restrict__ out) {
    int flat = blockIdx.x * 256 + threadIdx.x;
    if (flat >= N_EFLOAT4) return;
    int s = flat / 80;               // (b*50+k)*64 + i   (0..102399)
    int q = flat - s * 80;           // float4 within 320-float row
    int i = s & 63;
    int bk = s >> 6;                 // b*50 + k
    int k = bk % 50;

    const unsigned char* labRow = g_lab + (size_t)s * 64;  // = [b][k][i][*]
    int f0 = q * 4;
    float4 v;
    {
        float* vp = &v.x;
#pragma unroll
        for (int t = 0; t < 4; t++) {
            int f = f0 + t;
            int cl = f / 5;                  // j coordinate
            int ch = f - cl * 5;             // class index
            int L = (cl == i) ? 255 : (int)labRow[cl];
            vp[t] = (ch == L) ? 1.0f : 0.0f;
        }
    }
    *(float4*)(out + OFF_EN + (size_t)s * 320 + f0) = v;
    if (k < 49) {
        *(float4*)(out + OFF_EC + (size_t)(s + 64) * 320 + f0) = v;
    } else {
        int b = bk / 50;
        int s0 = s - 49 * 64;                // (b*50+0)*64 + i
        float4 raw = *(const float4*)(E + (size_t)b * 20480 + (size_t)i * 320 + f0);
        *(float4*)(out + OFF_EC + (size_t)s0 * 320 + f0) = raw;
    }
}

extern "C" void kernel_launch(void* const* d_in, const int* in_sizes, int n_in,
                              void* d_out, int out_size) {
    (void)in_sizes; (void)n_in; (void)out_size;
    const float* X      = (const float*)d_in[0];
    const float* E      = (const float*)d_in[1];
    const void*  maskp  = d_in[2];
    const float* gammas = (const float*)d_in[3];
    const float* Wx     = (const float*)d_in[4];
    const float* We     = (const float*)d_in[5];
    float* out = (float*)d_out;

    // 1008 edge blocks (64512 chains x 2 lanes) + 64 node blocks (2048 x 4)
    chain_kernel<<<EDGE_BLOCKS + 64, 128>>>(X, E, maskp, gammas, Wx, We, out);
    // 8,192,000 float4 / 256 = 32000 blocks
    expand_kernel<<<32000, 256>>>(E, out);
}